// round 2
// baseline (speedup 1.0000x reference)
#include <cuda_runtime.h>
#include <cstdint>
#include <cstddef>

#define NB 64
#define TT 512
#define NV 2048
#define NH 1024
#define G3 3072
#define SCAN_BLOCKS 128
#define JPB 8
#define HID_ELEMS ((size_t)NB * TT * NH)

// ---------------- device scratch (module-static; no runtime allocation) -----
__device__ float g_h[2][NB * NH];                 // double-buffered hidden state
__device__ float g_tokgi[(size_t)NV * G3];        // per-token gi precompute (25 MB)
__device__ int g_y64;                             // 1 if y is int64, 0 if int32
__device__ unsigned g_bar_count;
__device__ volatile unsigned g_bar_gen;

// ---------------- y dtype detection + barrier reset --------------------------
// Interpret the y buffer as int64 pairs. If y is really int32, some pair has a
// nonzero hi-word (tokens in [0,2048)) -> value >= 2^32 -> flagged. Scans
// 16384 int64 slots = 128KB, within bounds for either dtype.
__global__ void detect_reset_kernel(const long long* __restrict__ y) {
    __shared__ int bad;
    if (threadIdx.x == 0) { bad = 0; g_bar_count = 0u; g_bar_gen = 0u; }
    __syncthreads();
    int local = 0;
    for (int i = threadIdx.x; i < (NB * TT) / 2; i += blockDim.x) {
        long long v = y[i];
        if (v < 0 || v >= NV) local = 1;
    }
    if (local) atomicExch(&bad, 1);
    __syncthreads();
    if (threadIdx.x == 0) g_y64 = bad ? 0 : 1;
}

// ---------------- fp32 SGEMM (NT): C[M,N] = A[M,K] * B[N,K]^T (+bias[N]) -----
// 128x128 tile, BK=16, 256 threads, 8x8 microtile (split 4+4 for conflict-free
// LDS.128). Requires K%16==0, N%128==0; M arbitrary.
__global__ void __launch_bounds__(256) sgemm_nt_bias(
    const float* __restrict__ A, const float* __restrict__ Bm,
    const float* __restrict__ bias, float* __restrict__ C,
    int M, int N, int K)
{
    __shared__ float As[16][132];
    __shared__ float Bs[16][132];
    const int tid = threadIdx.x;
    const int tx = tid & 15, ty = tid >> 4;
    const int m0 = blockIdx.y * 128, n0 = blockIdx.x * 128;

    float acc[8][8];
#pragma unroll
    for (int i = 0; i < 8; i++)
#pragma unroll
        for (int j = 0; j < 8; j++) acc[i][j] = 0.f;

    for (int k0 = 0; k0 < K; k0 += 16) {
#pragma unroll
        for (int r = 0; r < 2; r++) {
            int v = tid + r * 256;           // 0..511
            int row = v >> 2;                // 0..127
            int kv = (v & 3) << 2;           // 0,4,8,12
            int gm = m0 + row;
            float4 a = make_float4(0.f, 0.f, 0.f, 0.f);
            if (gm < M) a = *(const float4*)(A + (size_t)gm * K + k0 + kv);
            As[kv + 0][row] = a.x; As[kv + 1][row] = a.y;
            As[kv + 2][row] = a.z; As[kv + 3][row] = a.w;
            int gn = n0 + row;               // N%128==0 -> always valid
            float4 b = *(const float4*)(Bm + (size_t)gn * K + k0 + kv);
            Bs[kv + 0][row] = b.x; Bs[kv + 1][row] = b.y;
            Bs[kv + 2][row] = b.z; Bs[kv + 3][row] = b.w;
        }
        __syncthreads();
#pragma unroll
        for (int kk = 0; kk < 16; kk++) {
            float af[8], bf[8];
            *(float4*)&af[0] = *(const float4*)&As[kk][ty * 4];
            *(float4*)&af[4] = *(const float4*)&As[kk][64 + ty * 4];
            *(float4*)&bf[0] = *(const float4*)&Bs[kk][tx * 4];
            *(float4*)&bf[4] = *(const float4*)&Bs[kk][64 + tx * 4];
#pragma unroll
            for (int i = 0; i < 8; i++)
#pragma unroll
                for (int j = 0; j < 8; j++) acc[i][j] = fmaf(af[i], bf[j], acc[i][j]);
        }
        __syncthreads();
    }

#pragma unroll
    for (int i = 0; i < 8; i++) {
        int gm = m0 + ((i < 4) ? (ty * 4 + i) : (64 + ty * 4 + i - 4));
        if (gm >= M) continue;
        int n1 = n0 + tx * 4;
        int n2 = n0 + 64 + tx * 4;
        float4 o1, o2;
        o1.x = acc[i][0]; o1.y = acc[i][1]; o1.z = acc[i][2]; o1.w = acc[i][3];
        o2.x = acc[i][4]; o2.y = acc[i][5]; o2.z = acc[i][6]; o2.w = acc[i][7];
        if (bias) {
            o1.x += bias[n1 + 0]; o1.y += bias[n1 + 1];
            o1.z += bias[n1 + 2]; o1.w += bias[n1 + 3];
            o2.x += bias[n2 + 0]; o2.y += bias[n2 + 1];
            o2.z += bias[n2 + 2]; o2.w += bias[n2 + 3];
        }
        *(float4*)(C + (size_t)gm * N + n1) = o1;
        *(float4*)(C + (size_t)gm * N + n2) = o2;
    }
}

// ---------------- grid barrier (all SCAN_BLOCKS co-resident) -----------------
__device__ __forceinline__ void grid_barrier(unsigned target) {
    __syncthreads();
    if (threadIdx.x == 0) {
        __threadfence();
        unsigned prev = atomicAdd(&g_bar_count, 1u);
        if (prev == (unsigned)(SCAN_BLOCKS - 1)) {
            g_bar_count = 0u;
            __threadfence();
            g_bar_gen = target;
        } else {
            while (g_bar_gen < target) __nanosleep(32);
        }
        __threadfence();
    }
    __syncthreads();
}

// ---------------- persistent GRU scan ----------------------------------------
// 128 blocks x 256 threads. Block owns hidden units [jbase, jbase+8).
// Thread (kp=tid>>5, rg=(tid>>3)&3, bg=tid&7):
//   accumulation: batches bg*8..bg*8+7, gate-rows u=rg*6..rg*6+5 (unit-major:
//   u = jl*3+g), k-slice kp*128..+127  -> 48 partial dots in registers.
//   reduction: conflict-free smem red[c][tid], sum over 8 kp-warps.
//   gate phase: thread handles batch bg*8+kp, units 2rg, 2rg+1 (full r/z/n).
__global__ void __launch_bounds__(256, 1) gru_scan_kernel(
    const float* __restrict__ w_hh, const float* __restrict__ b_hh,
    const void* __restrict__ y_any, float* __restrict__ out_hidden)
{
    __shared__ float red[48 * 256];   // 48KB, [c][tid]
    const int tid = threadIdx.x;
    const int kp = tid >> 5;
    const int lane = tid & 31;
    const int rg = lane >> 3;
    const int bg = lane & 7;
    const int jbase = blockIdx.x * JPB;

    // W row pointers for this thread's 6 gate-rows (fixed across steps)
    const float* wrow[6];
#pragma unroll
    for (int j = 0; j < 6; j++) {
        int u = rg * 6 + j;                       // unit-major: u = jl*3 + g
        int row = (u % 3) * NH + jbase + (u / 3); // global w_hh row
        wrow[j] = w_hh + (size_t)row * NH;
    }

    // gate-phase constants
    const int b_gate = bg * 8 + kp;
    const int jl0 = rg * 2;
    float bh[2][3];
#pragma unroll
    for (int q = 0; q < 2; q++) {
        int gj = jbase + jl0 + q;
        bh[q][0] = b_hh[gj];
        bh[q][1] = b_hh[NH + gj];
        bh[q][2] = b_hh[2 * NH + gj];
    }
    const int use64 = g_y64;
    const int* y32 = (const int*)y_any;
    const long long* y64p = (const long long*)y_any;
    const int k0 = kp * 128;

    for (int t = 0; t < TT; t++) {
        const float* __restrict__ hcur = g_h[t & 1];
        float* __restrict__ hnxt = g_h[(t & 1) ^ 1];

        float acc[8][6];
#pragma unroll
        for (int i = 0; i < 8; i++)
#pragma unroll
            for (int j = 0; j < 6; j++) acc[i][j] = 0.f;

        for (int k = k0; k < k0 + 128; k += 4) {
            float4 wv[6];
#pragma unroll
            for (int j = 0; j < 6; j++) wv[j] = *(const float4*)(wrow[j] + k);
#pragma unroll
            for (int i = 0; i < 8; i++) {
                float4 hv = *(const float4*)(hcur + (size_t)(bg * 8 + i) * NH + k);
#pragma unroll
                for (int j = 0; j < 6; j++) {
                    acc[i][j] = fmaf(hv.x, wv[j].x, acc[i][j]);
                    acc[i][j] = fmaf(hv.y, wv[j].y, acc[i][j]);
                    acc[i][j] = fmaf(hv.z, wv[j].z, acc[i][j]);
                    acc[i][j] = fmaf(hv.w, wv[j].w, acc[i][j]);
                }
            }
        }

        // stage partials: red[c*256 + tid] (writes conflict-free)
#pragma unroll
        for (int i = 0; i < 8; i++)
#pragma unroll
            for (int j = 0; j < 6; j++) red[(i * 6 + j) * 256 + tid] = acc[i][j];
        __syncthreads();

        // reduce over the 8 kp-warps (reads conflict-free: lane-contiguous)
        float gh[6];
#pragma unroll
        for (int j = 0; j < 6; j++) {
            int c = kp * 6 + j;    // i==kp  ->  batch bg*8+kp
            float s = 0.f;
#pragma unroll
            for (int kq = 0; kq < 8; kq++) s += red[c * 256 + kq * 32 + lane];
            gh[j] = s;
        }

        int tok = 0;
        if (t > 0) tok = use64 ? (int)y64p[(size_t)b_gate * TT + t - 1]
                               : y32[(size_t)b_gate * TT + t - 1];
        const float* gi = g_tokgi + (size_t)tok * G3;

#pragma unroll
        for (int q = 0; q < 2; q++) {
            int gj = jbase + jl0 + q;
            float i_r = gi[gj], i_z = gi[NH + gj], i_n = gi[2 * NH + gj];
            float h_r = gh[q * 3 + 0] + bh[q][0];
            float h_z = gh[q * 3 + 1] + bh[q][1];
            float h_n = gh[q * 3 + 2] + bh[q][2];
            float r = 1.f / (1.f + __expf(-(i_r + h_r)));
            float z = 1.f / (1.f + __expf(-(i_z + h_z)));
            float xn = i_n + r * h_n;
            float e2 = __expf(-2.f * xn);       // tanh, inf-safe at both ends
            float n = 2.f / (1.f + e2) - 1.f;
            float hp = hcur[(size_t)b_gate * NH + gj];
            float hn = (1.f - z) * n + z * hp;
            hnxt[(size_t)b_gate * NH + gj] = hn;
            out_hidden[((size_t)b_gate * TT + t) * NH + gj] = hn;
        }

        grid_barrier((unsigned)(t + 1));
    }
}

// ---------------- in-place log-softmax over V=2048 ---------------------------
__global__ void __launch_bounds__(256) logsoftmax_kernel(float* __restrict__ p) {
    const size_t row = blockIdx.x;
    float* x = p + row * NV;
    const int tid = threadIdx.x;
    float4 v0 = ((const float4*)x)[tid];
    float4 v1 = ((const float4*)x)[tid + 256];
    float m = fmaxf(fmaxf(fmaxf(v0.x, v0.y), fmaxf(v0.z, v0.w)),
                    fmaxf(fmaxf(v1.x, v1.y), fmaxf(v1.z, v1.w)));
    __shared__ float sred[32];
#pragma unroll
    for (int o = 16; o; o >>= 1) m = fmaxf(m, __shfl_xor_sync(0xffffffffu, m, o));
    if ((tid & 31) == 0) sred[tid >> 5] = m;
    __syncthreads();
    if (tid < 32) {
        float t2 = (tid < 8) ? sred[tid] : -3.4e38f;
#pragma unroll
        for (int o = 4; o; o >>= 1) t2 = fmaxf(t2, __shfl_xor_sync(0xffffffffu, t2, o));
        if (tid == 0) sred[0] = t2;
    }
    __syncthreads();
    m = sred[0];
    float s = __expf(v0.x - m) + __expf(v0.y - m) + __expf(v0.z - m) + __expf(v0.w - m)
            + __expf(v1.x - m) + __expf(v1.y - m) + __expf(v1.z - m) + __expf(v1.w - m);
    __syncthreads();
#pragma unroll
    for (int o = 16; o; o >>= 1) s += __shfl_xor_sync(0xffffffffu, s, o);
    if ((tid & 31) == 0) sred[tid >> 5] = s;
    __syncthreads();
    if (tid < 32) {
        float t2 = (tid < 8) ? sred[tid] : 0.f;
#pragma unroll
        for (int o = 4; o; o >>= 1) t2 += __shfl_xor_sync(0xffffffffu, t2, o);
        if (tid == 0) sred[0] = t2;
    }
    __syncthreads();
    float lse = m + logf(sred[0]);
    v0.x -= lse; v0.y -= lse; v0.z -= lse; v0.w -= lse;
    v1.x -= lse; v1.y -= lse; v1.z -= lse; v1.w -= lse;
    ((float4*)x)[tid] = v0;
    ((float4*)x)[tid + 256] = v1;
}

// ---------------- launch ------------------------------------------------------
extern "C" void kernel_launch(void* const* d_in, const int* in_sizes, int n_in,
                              void* d_out, int out_size) {
    // input order: enc, y, [max_length], emb_table, bridge_W, bridge_b,
    //              w_ih, w_hh, b_ih, b_hh, fc_W
    int o = (n_in >= 11) ? 1 : 0;
    const float* enc  = (const float*)d_in[0];
    const void*  y    = d_in[1];
    const float* emb  = (const float*)d_in[2 + o];
    const float* brW  = (const float*)d_in[3 + o];
    const float* brb  = (const float*)d_in[4 + o];
    const float* w_ih = (const float*)d_in[5 + o];
    const float* w_hh = (const float*)d_in[6 + o];
    const float* b_ih = (const float*)d_in[7 + o];
    const float* b_hh = (const float*)d_in[8 + o];
    const float* fcW  = (const float*)d_in[9 + o];

    float* out = (float*)d_out;
    float* out_hidden = out;                       // [64,512,1024]
    float* out_logits = out + HID_ELEMS;           // [64,512,2048]

    void* p_h = nullptr;   cudaGetSymbolAddress(&p_h, g_h);
    void* p_tok = nullptr; cudaGetSymbolAddress(&p_tok, g_tokgi);

    dim3 blk(256);
    detect_reset_kernel<<<1, 256>>>((const long long*)y);
    // tokgi[v] = emb[v] @ w_ih^T + b_ih   (M=2048, N=3072, K=256)
    sgemm_nt_bias<<<dim3(G3 / 128, NV / 128), blk>>>(emb, w_ih, b_ih,
                                                     (float*)p_tok, NV, G3, 256);
    // h0 = enc @ bridge_W^T + bridge_b    (M=64, N=1024, K=512)
    sgemm_nt_bias<<<dim3(NH / 128, 1), blk>>>(enc, brW, brb,
                                              (float*)p_h, NB, NH, 512);
    // persistent GRU recurrence (writes out_hidden)
    gru_scan_kernel<<<SCAN_BLOCKS, 256>>>(w_hh, b_hh, y, out_hidden);
    // logits = hidden @ fc_W^T            (M=32768, N=2048, K=1024), in-place
    sgemm_nt_bias<<<dim3(NV / 128, (NB * TT) / 128), blk>>>(out_hidden, fcW,
                                                            nullptr, out_logits,
                                                            NB * TT, NV, NH);
    // in-place log-softmax
    logsoftmax_kernel<<<NB * TT, 256>>>(out_logits);
}

// round 4
// speedup vs baseline: 1.0797x; 1.0797x over previous
#include <cuda_runtime.h>
#include <cstdint>
#include <cstddef>

#define NB 64
#define TT 512
#define NV 2048
#define NH 1024
#define G3 3072
#define SCAN_BLOCKS 128
#define JPB 8
#define HID_ELEMS ((size_t)NB * TT * NH)

// ---------------- device scratch (module-static; no runtime allocation) -----
__device__ float g_h[2][NB * NH];                 // double-buffered hidden state
__device__ float g_tokgi[(size_t)NV * G3];        // per-token gi precompute (25 MB)
__device__ int g_y64;                             // 1 if y is int64, 0 if int32
__device__ unsigned g_bar_count;
__device__ volatile unsigned g_bar_gen;

// ---------------- y dtype detection + barrier reset --------------------------
__global__ void detect_reset_kernel(const long long* __restrict__ y) {
    __shared__ int bad;
    if (threadIdx.x == 0) { bad = 0; g_bar_count = 0u; g_bar_gen = 0u; }
    __syncthreads();
    int local = 0;
    for (int i = threadIdx.x; i < (NB * TT) / 2; i += blockDim.x) {
        long long v = y[i];
        if (v < 0 || v >= NV) local = 1;
    }
    if (local) atomicExch(&bad, 1);
    __syncthreads();
    if (threadIdx.x == 0) g_y64 = bad ? 0 : 1;
}

// ---------------- fp32 SGEMM (NT): C[M,N] = A[M,K] * B[N,K]^T (+bias[N]) -----
// Used only for the small precision-critical GEMMs (tokgi, h0).
__global__ void __launch_bounds__(256) sgemm_nt_bias(
    const float* __restrict__ A, const float* __restrict__ Bm,
    const float* __restrict__ bias, float* __restrict__ C,
    int M, int N, int K)
{
    __shared__ float As[16][132];
    __shared__ float Bs[16][132];
    const int tid = threadIdx.x;
    const int tx = tid & 15, ty = tid >> 4;
    const int m0 = blockIdx.y * 128, n0 = blockIdx.x * 128;

    float acc[8][8];
#pragma unroll
    for (int i = 0; i < 8; i++)
#pragma unroll
        for (int j = 0; j < 8; j++) acc[i][j] = 0.f;

    for (int k0 = 0; k0 < K; k0 += 16) {
#pragma unroll
        for (int r = 0; r < 2; r++) {
            int v = tid + r * 256;
            int row = v >> 2;
            int kv = (v & 3) << 2;
            int gm = m0 + row;
            float4 a = make_float4(0.f, 0.f, 0.f, 0.f);
            if (gm < M) a = *(const float4*)(A + (size_t)gm * K + k0 + kv);
            As[kv + 0][row] = a.x; As[kv + 1][row] = a.y;
            As[kv + 2][row] = a.z; As[kv + 3][row] = a.w;
            int gn = n0 + row;
            float4 b = *(const float4*)(Bm + (size_t)gn * K + k0 + kv);
            Bs[kv + 0][row] = b.x; Bs[kv + 1][row] = b.y;
            Bs[kv + 2][row] = b.z; Bs[kv + 3][row] = b.w;
        }
        __syncthreads();
#pragma unroll
        for (int kk = 0; kk < 16; kk++) {
            float af[8], bf[8];
            *(float4*)&af[0] = *(const float4*)&As[kk][ty * 4];
            *(float4*)&af[4] = *(const float4*)&As[kk][64 + ty * 4];
            *(float4*)&bf[0] = *(const float4*)&Bs[kk][tx * 4];
            *(float4*)&bf[4] = *(const float4*)&Bs[kk][64 + tx * 4];
#pragma unroll
            for (int i = 0; i < 8; i++)
#pragma unroll
                for (int j = 0; j < 8; j++) acc[i][j] = fmaf(af[i], bf[j], acc[i][j]);
        }
        __syncthreads();
    }

#pragma unroll
    for (int i = 0; i < 8; i++) {
        int gm = m0 + ((i < 4) ? (ty * 4 + i) : (64 + ty * 4 + i - 4));
        if (gm >= M) continue;
        int n1 = n0 + tx * 4;
        int n2 = n0 + 64 + tx * 4;
        float4 o1, o2;
        o1.x = acc[i][0]; o1.y = acc[i][1]; o1.z = acc[i][2]; o1.w = acc[i][3];
        o2.x = acc[i][4]; o2.y = acc[i][5]; o2.z = acc[i][6]; o2.w = acc[i][7];
        if (bias) {
            o1.x += bias[n1 + 0]; o1.y += bias[n1 + 1];
            o1.z += bias[n1 + 2]; o1.w += bias[n1 + 3];
            o2.x += bias[n2 + 0]; o2.y += bias[n2 + 1];
            o2.z += bias[n2 + 2]; o2.w += bias[n2 + 3];
        }
        *(float4*)(C + (size_t)gm * N + n1) = o1;
        *(float4*)(C + (size_t)gm * N + n2) = o2;
    }
}

// ---------------- tf32 tensor-core GEMM (NT): C = A[M,K] * B[N,K]^T ----------
// 128x128 block tile, BK=16, 2-stage cp.async pipeline, 8 warps (2m x 4n),
// warp tile 64x32 via mma.sync.m16n8k8 tf32. Requires M%128==0, N%128==0,
// K%16==0. SMEM float4-XOR swizzle, conflict-free for the mma fragment pattern.
__device__ __forceinline__ uint32_t f2tf32(float x) {
    uint32_t r;
    asm("cvt.rna.tf32.f32 %0, %1;" : "=r"(r) : "f"(x));
    return r;
}
__device__ __forceinline__ void cpasync16(void* sdst, const void* gsrc) {
    uint32_t sa = (uint32_t)__cvta_generic_to_shared(sdst);
    asm volatile("cp.async.cg.shared.global [%0], [%1], 16;\n" :: "r"(sa), "l"(gsrc));
}
__device__ __forceinline__ void cpasync_commit() {
    asm volatile("cp.async.commit_group;\n" ::: "memory");
}
template<int NLeft>
__device__ __forceinline__ void cpasync_wait() {
    asm volatile("cp.async.wait_group %0;\n" :: "n"(NLeft) : "memory");
}

__global__ void __launch_bounds__(256) gemm_tf32_nt(
    const float* __restrict__ A, const float* __restrict__ Bm,
    float* __restrict__ C, int M, int N, int K)
{
    __shared__ float4 As[2][512];   // [stage][row*4 + swizzled_c]  128x16 floats
    __shared__ float4 Bs[2][512];

    const int tid = threadIdx.x;
    const int wid = tid >> 5;
    const int lane = tid & 31;
    const int lr = lane >> 2;       // 0..7
    const int lw = lane & 3;        // 0..3
    const int sw = lr >> 1;         // swizzle term for fragment loads
    const int warp_m = wid >> 2;    // 0..1 -> m offset *64
    const int warp_n = wid & 3;     // 0..3 -> n offset *32
    const int m0 = blockIdx.y * 128, n0 = blockIdx.x * 128;

    const int row_l = tid >> 2;     // 0..63 (x2 iters -> 0..127) for loads
    const int c_l = tid & 3;

    float acc[4][4][4];
#pragma unroll
    for (int i = 0; i < 4; i++)
#pragma unroll
        for (int j = 0; j < 4; j++)
#pragma unroll
            for (int q = 0; q < 4; q++) acc[i][j][q] = 0.f;

    const int NC = K >> 4;          // 16-k chunks

    // issue loads for one stage
    auto issue = [&](int st, int k0) {
#pragma unroll
        for (int r = 0; r < 2; r++) {
            int row = row_l + r * 64;
            int cs = c_l ^ ((row & 7) >> 1);
            cpasync16(&As[st][row * 4 + cs],
                      A + (size_t)(m0 + row) * K + k0 + c_l * 4);
            cpasync16(&Bs[st][row * 4 + cs],
                      Bm + (size_t)(n0 + row) * K + k0 + c_l * 4);
        }
        cpasync_commit();
    };

    issue(0, 0);

    for (int ch = 0; ch < NC; ch++) {
        if (ch + 1 < NC) issue((ch + 1) & 1, (ch + 1) << 4);
        if (ch + 1 < NC) cpasync_wait<1>(); else cpasync_wait<0>();
        __syncthreads();

        const float* as = (const float*)As[ch & 1];
        const float* bs = (const float*)Bs[ch & 1];

#pragma unroll
        for (int ks = 0; ks < 2; ks++) {
            uint32_t af[4][4];
#pragma unroll
            for (int i = 0; i < 4; i++) {
                int rbase = warp_m * 64 + i * 16 + lr;
                int i0 = rbase * 16 + ((2 * ks) ^ sw) * 4 + lw;
                int i2 = rbase * 16 + ((2 * ks + 1) ^ sw) * 4 + lw;
                af[i][0] = f2tf32(as[i0]);
                af[i][1] = f2tf32(as[i0 + 128]);
                af[i][2] = f2tf32(as[i2]);
                af[i][3] = f2tf32(as[i2 + 128]);
            }
            uint32_t bf[4][2];
#pragma unroll
            for (int j = 0; j < 4; j++) {
                int rbase = warp_n * 32 + j * 8 + lr;
                int i0 = rbase * 16 + ((2 * ks) ^ sw) * 4 + lw;
                int i1 = rbase * 16 + ((2 * ks + 1) ^ sw) * 4 + lw;
                bf[j][0] = f2tf32(bs[i0]);
                bf[j][1] = f2tf32(bs[i1]);
            }
#pragma unroll
            for (int i = 0; i < 4; i++)
#pragma unroll
                for (int j = 0; j < 4; j++) {
                    asm volatile(
                        "mma.sync.aligned.m16n8k8.row.col.f32.tf32.tf32.f32 "
                        "{%0,%1,%2,%3}, {%4,%5,%6,%7}, {%8,%9}, {%0,%1,%2,%3};"
                        : "+f"(acc[i][j][0]), "+f"(acc[i][j][1]),
                          "+f"(acc[i][j][2]), "+f"(acc[i][j][3])
                        : "r"(af[i][0]), "r"(af[i][1]), "r"(af[i][2]), "r"(af[i][3]),
                          "r"(bf[j][0]), "r"(bf[j][1]));
                }
        }
        __syncthreads();
    }

    // epilogue: c0/c1 -> (row, 2*lw), c2/c3 -> (row+8, 2*lw)
#pragma unroll
    for (int i = 0; i < 4; i++) {
        int row0 = m0 + warp_m * 64 + i * 16 + lr;
#pragma unroll
        for (int j = 0; j < 4; j++) {
            int col = n0 + warp_n * 32 + j * 8 + lw * 2;
            float2 lo, hi;
            lo.x = acc[i][j][0]; lo.y = acc[i][j][1];
            hi.x = acc[i][j][2]; hi.y = acc[i][j][3];
            *(float2*)(C + (size_t)row0 * N + col) = lo;
            *(float2*)(C + (size_t)(row0 + 8) * N + col) = hi;
        }
    }
}

// ---------------- grid barrier (all SCAN_BLOCKS co-resident) -----------------
__device__ __forceinline__ void grid_barrier(unsigned target) {
    __syncthreads();
    if (threadIdx.x == 0) {
        __threadfence();
        unsigned prev = atomicAdd(&g_bar_count, 1u);
        if (prev == (unsigned)(SCAN_BLOCKS - 1)) {
            g_bar_count = 0u;
            __threadfence();
            g_bar_gen = target;
        } else {
            while (g_bar_gen < target) __nanosleep(32);
        }
        __threadfence();
    }
    __syncthreads();
}

// ---------------- persistent GRU scan ----------------------------------------
__global__ void __launch_bounds__(256, 1) gru_scan_kernel(
    const float* __restrict__ w_hh, const float* __restrict__ b_hh,
    const void* __restrict__ y_any, float* __restrict__ out_hidden)
{
    __shared__ float red[48 * 256];
    const int tid = threadIdx.x;
    const int kp = tid >> 5;
    const int lane = tid & 31;
    const int rg = lane >> 3;
    const int bg = lane & 7;
    const int jbase = blockIdx.x * JPB;

    const float* wrow[6];
#pragma unroll
    for (int j = 0; j < 6; j++) {
        int u = rg * 6 + j;
        int row = (u % 3) * NH + jbase + (u / 3);
        wrow[j] = w_hh + (size_t)row * NH;
    }

    const int b_gate = bg * 8 + kp;
    const int jl0 = rg * 2;
    float bh[2][3];
#pragma unroll
    for (int q = 0; q < 2; q++) {
        int gj = jbase + jl0 + q;
        bh[q][0] = b_hh[gj];
        bh[q][1] = b_hh[NH + gj];
        bh[q][2] = b_hh[2 * NH + gj];
    }
    const int use64 = g_y64;
    const int* y32 = (const int*)y_any;
    const long long* y64p = (const long long*)y_any;
    const int k0 = kp * 128;

    for (int t = 0; t < TT; t++) {
        const float* __restrict__ hcur = g_h[t & 1];
        float* __restrict__ hnxt = g_h[(t & 1) ^ 1];

        float acc[8][6];
#pragma unroll
        for (int i = 0; i < 8; i++)
#pragma unroll
            for (int j = 0; j < 6; j++) acc[i][j] = 0.f;

        for (int k = k0; k < k0 + 128; k += 4) {
            float4 wv[6];
#pragma unroll
            for (int j = 0; j < 6; j++) wv[j] = *(const float4*)(wrow[j] + k);
#pragma unroll
            for (int i = 0; i < 8; i++) {
                float4 hv = *(const float4*)(hcur + (size_t)(bg * 8 + i) * NH + k);
#pragma unroll
                for (int j = 0; j < 6; j++) {
                    acc[i][j] = fmaf(hv.x, wv[j].x, acc[i][j]);
                    acc[i][j] = fmaf(hv.y, wv[j].y, acc[i][j]);
                    acc[i][j] = fmaf(hv.z, wv[j].z, acc[i][j]);
                    acc[i][j] = fmaf(hv.w, wv[j].w, acc[i][j]);
                }
            }
        }

#pragma unroll
        for (int i = 0; i < 8; i++)
#pragma unroll
            for (int j = 0; j < 6; j++) red[(i * 6 + j) * 256 + tid] = acc[i][j];
        __syncthreads();

        float gh[6];
#pragma unroll
        for (int j = 0; j < 6; j++) {
            int c = kp * 6 + j;
            float s = 0.f;
#pragma unroll
            for (int kq = 0; kq < 8; kq++) s += red[c * 256 + kq * 32 + lane];
            gh[j] = s;
        }

        int tok = 0;
        if (t > 0) tok = use64 ? (int)y64p[(size_t)b_gate * TT + t - 1]
                               : y32[(size_t)b_gate * TT + t - 1];
        const float* gi = g_tokgi + (size_t)tok * G3;

#pragma unroll
        for (int q = 0; q < 2; q++) {
            int gj = jbase + jl0 + q;
            float i_r = gi[gj], i_z = gi[NH + gj], i_n = gi[2 * NH + gj];
            float h_r = gh[q * 3 + 0] + bh[q][0];
            float h_z = gh[q * 3 + 1] + bh[q][1];
            float h_n = gh[q * 3 + 2] + bh[q][2];
            float r = 1.f / (1.f + __expf(-(i_r + h_r)));
            float z = 1.f / (1.f + __expf(-(i_z + h_z)));
            float xn = i_n + r * h_n;
            float e2 = __expf(-2.f * xn);
            float n = 2.f / (1.f + e2) - 1.f;
            float hp = hcur[(size_t)b_gate * NH + gj];
            float hn = (1.f - z) * n + z * hp;
            hnxt[(size_t)b_gate * NH + gj] = hn;
            out_hidden[((size_t)b_gate * TT + t) * NH + gj] = hn;
        }

        grid_barrier((unsigned)(t + 1));
    }
}

// ---------------- in-place log-softmax over V=2048 ---------------------------
__global__ void __launch_bounds__(256) logsoftmax_kernel(float* __restrict__ p) {
    const size_t row = blockIdx.x;
    float* x = p + row * NV;
    const int tid = threadIdx.x;
    float4 v0 = ((const float4*)x)[tid];
    float4 v1 = ((const float4*)x)[tid + 256];
    float m = fmaxf(fmaxf(fmaxf(v0.x, v0.y), fmaxf(v0.z, v0.w)),
                    fmaxf(fmaxf(v1.x, v1.y), fmaxf(v1.z, v1.w)));
    __shared__ float sred[32];
#pragma unroll
    for (int o = 16; o; o >>= 1) m = fmaxf(m, __shfl_xor_sync(0xffffffffu, m, o));
    if ((tid & 31) == 0) sred[tid >> 5] = m;
    __syncthreads();
    if (tid < 32) {
        float t2 = (tid < 8) ? sred[tid] : -3.4e38f;
#pragma unroll
        for (int o = 4; o; o >>= 1) t2 = fmaxf(t2, __shfl_xor_sync(0xffffffffu, t2, o));
        if (tid == 0) sred[0] = t2;
    }
    __syncthreads();
    m = sred[0];
    float s = __expf(v0.x - m) + __expf(v0.y - m) + __expf(v0.z - m) + __expf(v0.w - m)
            + __expf(v1.x - m) + __expf(v1.y - m) + __expf(v1.z - m) + __expf(v1.w - m);
    __syncthreads();
#pragma unroll
    for (int o = 16; o; o >>= 1) s += __shfl_xor_sync(0xffffffffu, s, o);
    if ((tid & 31) == 0) sred[tid >> 5] = s;
    __syncthreads();
    if (tid < 32) {
        float t2 = (tid < 8) ? sred[tid] : 0.f;
#pragma unroll
        for (int o = 4; o; o >>= 1) t2 += __shfl_xor_sync(0xffffffffu, t2, o);
        if (tid == 0) sred[0] = t2;
    }
    __syncthreads();
    float lse = m + logf(sred[0]);
    v0.x -= lse; v0.y -= lse; v0.z -= lse; v0.w -= lse;
    v1.x -= lse; v1.y -= lse; v1.z -= lse; v1.w -= lse;
    ((float4*)x)[tid] = v0;
    ((float4*)x)[tid + 256] = v1;
}

// ---------------- launch ------------------------------------------------------
extern "C" void kernel_launch(void* const* d_in, const int* in_sizes, int n_in,
                              void* d_out, int out_size) {
    int o = (n_in >= 11) ? 1 : 0;
    const float* enc  = (const float*)d_in[0];
    const void*  y    = d_in[1];
    const float* emb  = (const float*)d_in[2 + o];
    const float* brW  = (const float*)d_in[3 + o];
    const float* brb  = (const float*)d_in[4 + o];
    const float* w_ih = (const float*)d_in[5 + o];
    const float* w_hh = (const float*)d_in[6 + o];
    const float* b_ih = (const float*)d_in[7 + o];
    const float* b_hh = (const float*)d_in[8 + o];
    const float* fcW  = (const float*)d_in[9 + o];

    float* out = (float*)d_out;
    float* out_hidden = out;                       // [64,512,1024]
    float* out_logits = out + HID_ELEMS;           // [64,512,2048]

    void* p_h = nullptr;   cudaGetSymbolAddress(&p_h, g_h);
    void* p_tok = nullptr; cudaGetSymbolAddress(&p_tok, g_tokgi);

    dim3 blk(256);
    detect_reset_kernel<<<1, 256>>>((const long long*)y);
    // tokgi[v] = emb[v] @ w_ih^T + b_ih   (fp32: feeds the 512-step recurrence)
    sgemm_nt_bias<<<dim3(G3 / 128, NV / 128), blk>>>(emb, w_ih, b_ih,
                                                     (float*)p_tok, NV, G3, 256);
    // h0 = enc @ bridge_W^T + bridge_b    (fp32)
    sgemm_nt_bias<<<dim3(NH / 128, 1), blk>>>(enc, brW, brb,
                                              (float*)p_h, NB, NH, 512);
    // persistent GRU recurrence (fp32, writes out_hidden)
    gru_scan_kernel<<<SCAN_BLOCKS, 256>>>(w_hh, b_hh, y, out_hidden);
    // logits = hidden @ fc_W^T  (tf32 tensor cores, in-place into out_logits)
    gemm_tf32_nt<<<dim3(NV / 128, (NB * TT) / 128), blk>>>(out_hidden, fcW,
                                                           out_logits,
                                                           NB * TT, NV, NH);
    // in-place log-softmax
    logsoftmax_kernel<<<NB * TT, 256>>>(out_logits);
}

// round 5
// speedup vs baseline: 3.4381x; 3.1842x over previous
#include <cuda_runtime.h>
#include <cuda_bf16.h>
#include <cstdint>
#include <cstddef>

#define NB 64
#define TT 512
#define NV 2048
#define NH 1024
#define G3 3072
#define SCAN_BLOCKS 128
#define JPB 8
#define HID_ELEMS ((size_t)NB * TT * NH)

// ---------------- device scratch -------------------------------------------
__device__ float g_h[2][NB * NH];                      // fp32 hidden state (exact)
__device__ __nv_bfloat16 g_hbf_hi[2][NB * NH];         // bf16 split of h (MMA operand)
__device__ __nv_bfloat16 g_hbf_lo[2][NB * NH];
__device__ float g_tokgi[(size_t)NV * G3];             // per-token gi precompute (25 MB)
__device__ int g_y64;
__device__ unsigned g_bar_count;
__device__ volatile unsigned g_bar_gen;

// ---------------- smem layout for the scan kernel (bytes) -------------------
#define WS_STRIDE 1032                     // 1024 + 8 bf16 pad (16B rotate per row)
#define HS_STRIDE 136                      // 128 + 8 bf16 pad
#define OFF_WHI   0
#define OFF_WLO   (24 * WS_STRIDE * 2)                       // 49536
#define OFF_HS    (2 * 24 * WS_STRIDE * 2)                   // 99072
#define HS_MAT    (64 * HS_STRIDE * 2)                       // 17408 bytes per matrix
#define HS_STAGE  (2 * HS_MAT)                               // hi+lo = 34816
#define OFF_RED   (OFF_HS + 2 * HS_STAGE)                    // 168704
#define OFF_GH    (OFF_RED + 4 * 32 * 12 * 4)                // 174848
#define SMEM_SCAN (OFF_GH + 64 * 24 * 4)                     // 180992

// ---------------- y dtype detection + barrier reset -------------------------
__global__ void detect_reset_kernel(const long long* __restrict__ y) {
    __shared__ int bad;
    if (threadIdx.x == 0) { bad = 0; g_bar_count = 0u; g_bar_gen = 0u; }
    __syncthreads();
    int local = 0;
    for (int i = threadIdx.x; i < (NB * TT) / 2; i += blockDim.x) {
        long long v = y[i];
        if (v < 0 || v >= NV) local = 1;
    }
    if (local) atomicExch(&bad, 1);
    __syncthreads();
    if (threadIdx.x == 0) g_y64 = bad ? 0 : 1;
}

// ---------------- h0 -> bf16 split ------------------------------------------
__global__ void h0_convert_kernel() {
    int idx = (blockIdx.x * 256 + threadIdx.x) * 4;
    float4 v = *(const float4*)&g_h[0][idx];
    float x[4] = {v.x, v.y, v.z, v.w};
#pragma unroll
    for (int q = 0; q < 4; q++) {
        __nv_bfloat16 hi = __float2bfloat16(x[q]);
        __nv_bfloat16 lo = __float2bfloat16(x[q] - __bfloat162float(hi));
        g_hbf_hi[0][idx + q] = hi;
        g_hbf_lo[0][idx + q] = lo;
    }
}

// ---------------- fp32 SGEMM (NT) for precision-critical small GEMMs --------
__global__ void __launch_bounds__(256) sgemm_nt_bias(
    const float* __restrict__ A, const float* __restrict__ Bm,
    const float* __restrict__ bias, float* __restrict__ C,
    int M, int N, int K)
{
    __shared__ float As[16][132];
    __shared__ float Bs[16][132];
    const int tid = threadIdx.x;
    const int tx = tid & 15, ty = tid >> 4;
    const int m0 = blockIdx.y * 128, n0 = blockIdx.x * 128;

    float acc[8][8];
#pragma unroll
    for (int i = 0; i < 8; i++)
#pragma unroll
        for (int j = 0; j < 8; j++) acc[i][j] = 0.f;

    for (int k0 = 0; k0 < K; k0 += 16) {
#pragma unroll
        for (int r = 0; r < 2; r++) {
            int v = tid + r * 256;
            int row = v >> 2;
            int kv = (v & 3) << 2;
            int gm = m0 + row;
            float4 a = make_float4(0.f, 0.f, 0.f, 0.f);
            if (gm < M) a = *(const float4*)(A + (size_t)gm * K + k0 + kv);
            As[kv + 0][row] = a.x; As[kv + 1][row] = a.y;
            As[kv + 2][row] = a.z; As[kv + 3][row] = a.w;
            int gn = n0 + row;
            float4 b = *(const float4*)(Bm + (size_t)gn * K + k0 + kv);
            Bs[kv + 0][row] = b.x; Bs[kv + 1][row] = b.y;
            Bs[kv + 2][row] = b.z; Bs[kv + 3][row] = b.w;
        }
        __syncthreads();
#pragma unroll
        for (int kk = 0; kk < 16; kk++) {
            float af[8], bf[8];
            *(float4*)&af[0] = *(const float4*)&As[kk][ty * 4];
            *(float4*)&af[4] = *(const float4*)&As[kk][64 + ty * 4];
            *(float4*)&bf[0] = *(const float4*)&Bs[kk][tx * 4];
            *(float4*)&bf[4] = *(const float4*)&Bs[kk][64 + tx * 4];
#pragma unroll
            for (int i = 0; i < 8; i++)
#pragma unroll
                for (int j = 0; j < 8; j++) acc[i][j] = fmaf(af[i], bf[j], acc[i][j]);
        }
        __syncthreads();
    }

#pragma unroll
    for (int i = 0; i < 8; i++) {
        int gm = m0 + ((i < 4) ? (ty * 4 + i) : (64 + ty * 4 + i - 4));
        if (gm >= M) continue;
        int n1 = n0 + tx * 4;
        int n2 = n0 + 64 + tx * 4;
        float4 o1, o2;
        o1.x = acc[i][0]; o1.y = acc[i][1]; o1.z = acc[i][2]; o1.w = acc[i][3];
        o2.x = acc[i][4]; o2.y = acc[i][5]; o2.z = acc[i][6]; o2.w = acc[i][7];
        if (bias) {
            o1.x += bias[n1 + 0]; o1.y += bias[n1 + 1];
            o1.z += bias[n1 + 2]; o1.w += bias[n1 + 3];
            o2.x += bias[n2 + 0]; o2.y += bias[n2 + 1];
            o2.z += bias[n2 + 2]; o2.w += bias[n2 + 3];
        }
        *(float4*)(C + (size_t)gm * N + n1) = o1;
        *(float4*)(C + (size_t)gm * N + n2) = o2;
    }
}

// ---------------- async-copy helpers ----------------------------------------
__device__ __forceinline__ void cpasync16(void* sdst, const void* gsrc) {
    uint32_t sa = (uint32_t)__cvta_generic_to_shared(sdst);
    asm volatile("cp.async.cg.shared.global [%0], [%1], 16;\n" :: "r"(sa), "l"(gsrc));
}
__device__ __forceinline__ void cpasync_commit() {
    asm volatile("cp.async.commit_group;\n" ::: "memory");
}
template<int NLeft>
__device__ __forceinline__ void cpasync_wait() {
    asm volatile("cp.async.wait_group %0;\n" :: "n"(NLeft) : "memory");
}
__device__ __forceinline__ uint32_t f2tf32(float x) {
    uint32_t r;
    asm("cvt.rna.tf32.f32 %0, %1;" : "=r"(r) : "f"(x));
    return r;
}
__device__ __forceinline__ void mma_bf16(float* c, const uint32_t* a, const uint32_t* b) {
    asm volatile(
        "mma.sync.aligned.m16n8k16.row.col.f32.bf16.bf16.f32 "
        "{%0,%1,%2,%3}, {%4,%5,%6,%7}, {%8,%9}, {%0,%1,%2,%3};"
        : "+f"(c[0]), "+f"(c[1]), "+f"(c[2]), "+f"(c[3])
        : "r"(a[0]), "r"(a[1]), "r"(a[2]), "r"(a[3]), "r"(b[0]), "r"(b[1]));
}

// ---------------- tf32 tensor-core GEMM (NT): logits -------------------------
__global__ void __launch_bounds__(256) gemm_tf32_nt(
    const float* __restrict__ A, const float* __restrict__ Bm,
    float* __restrict__ C, int M, int N, int K)
{
    __shared__ float4 As[2][512];
    __shared__ float4 Bs[2][512];

    const int tid = threadIdx.x;
    const int wid = tid >> 5;
    const int lane = tid & 31;
    const int lr = lane >> 2;
    const int lw = lane & 3;
    const int sw = lr >> 1;
    const int warp_m = wid >> 2;
    const int warp_n = wid & 3;
    const int m0 = blockIdx.y * 128, n0 = blockIdx.x * 128;

    const int row_l = tid >> 2;
    const int c_l = tid & 3;

    float acc[4][4][4];
#pragma unroll
    for (int i = 0; i < 4; i++)
#pragma unroll
        for (int j = 0; j < 4; j++)
#pragma unroll
            for (int q = 0; q < 4; q++) acc[i][j][q] = 0.f;

    const int NC = K >> 4;

    auto issue = [&](int st, int k0) {
#pragma unroll
        for (int r = 0; r < 2; r++) {
            int row = row_l + r * 64;
            int cs = c_l ^ ((row & 7) >> 1);
            cpasync16(&As[st][row * 4 + cs], A + (size_t)(m0 + row) * K + k0 + c_l * 4);
            cpasync16(&Bs[st][row * 4 + cs], Bm + (size_t)(n0 + row) * K + k0 + c_l * 4);
        }
        cpasync_commit();
    };

    issue(0, 0);

    for (int ch = 0; ch < NC; ch++) {
        if (ch + 1 < NC) issue((ch + 1) & 1, (ch + 1) << 4);
        if (ch + 1 < NC) cpasync_wait<1>(); else cpasync_wait<0>();
        __syncthreads();

        const float* as = (const float*)As[ch & 1];
        const float* bs = (const float*)Bs[ch & 1];

#pragma unroll
        for (int ks = 0; ks < 2; ks++) {
            uint32_t af[4][4];
#pragma unroll
            for (int i = 0; i < 4; i++) {
                int rbase = warp_m * 64 + i * 16 + lr;
                int i0 = rbase * 16 + ((2 * ks) ^ sw) * 4 + lw;
                int i2 = rbase * 16 + ((2 * ks + 1) ^ sw) * 4 + lw;
                af[i][0] = f2tf32(as[i0]);
                af[i][1] = f2tf32(as[i0 + 128]);
                af[i][2] = f2tf32(as[i2]);
                af[i][3] = f2tf32(as[i2 + 128]);
            }
            uint32_t bf[4][2];
#pragma unroll
            for (int j = 0; j < 4; j++) {
                int rbase = warp_n * 32 + j * 8 + lr;
                int i0 = rbase * 16 + ((2 * ks) ^ sw) * 4 + lw;
                int i1 = rbase * 16 + ((2 * ks + 1) ^ sw) * 4 + lw;
                bf[j][0] = f2tf32(bs[i0]);
                bf[j][1] = f2tf32(bs[i1]);
            }
#pragma unroll
            for (int i = 0; i < 4; i++)
#pragma unroll
                for (int j = 0; j < 4; j++) {
                    asm volatile(
                        "mma.sync.aligned.m16n8k8.row.col.f32.tf32.tf32.f32 "
                        "{%0,%1,%2,%3}, {%4,%5,%6,%7}, {%8,%9}, {%0,%1,%2,%3};"
                        : "+f"(acc[i][j][0]), "+f"(acc[i][j][1]),
                          "+f"(acc[i][j][2]), "+f"(acc[i][j][3])
                        : "r"(af[i][0]), "r"(af[i][1]), "r"(af[i][2]), "r"(af[i][3]),
                          "r"(bf[j][0]), "r"(bf[j][1]));
                }
        }
        __syncthreads();
    }

#pragma unroll
    for (int i = 0; i < 4; i++) {
        int row0 = m0 + warp_m * 64 + i * 16 + lr;
#pragma unroll
        for (int j = 0; j < 4; j++) {
            int col = n0 + warp_n * 32 + j * 8 + lw * 2;
            float2 lo, hi;
            lo.x = acc[i][j][0]; lo.y = acc[i][j][1];
            hi.x = acc[i][j][2]; hi.y = acc[i][j][3];
            *(float2*)(C + (size_t)row0 * N + col) = lo;
            *(float2*)(C + (size_t)(row0 + 8) * N + col) = hi;
        }
    }
}

// ---------------- grid barrier ----------------------------------------------
__device__ __forceinline__ void grid_barrier(unsigned target) {
    __syncthreads();
    if (threadIdx.x == 0) {
        __threadfence();
        unsigned prev = atomicAdd(&g_bar_count, 1u);
        if (prev == (unsigned)(SCAN_BLOCKS - 1)) {
            g_bar_count = 0u;
            __threadfence();
            g_bar_gen = target;
        } else {
            while (g_bar_gen < target) __nanosleep(32);
        }
        __threadfence();
    }
    __syncthreads();
}

// ---------------- persistent GRU scan (bf16-split tensor cores) --------------
// Block b: units [b*8, b*8+8) -> 24 gate rows; n24 = gate*8 + unit_local.
// GH[64,24] per step via m16n8k16 bf16 MMA, 2-term bf16 split (3 MMAs).
// 8 warps = 4 m-tiles x 2 K-halves. W resident in SMEM as bf16 hi/lo.
__global__ void __launch_bounds__(256, 1) gru_scan_tc(
    const float* __restrict__ w_hh, const float* __restrict__ b_hh,
    const void* __restrict__ y_any, float* __restrict__ out_hidden)
{
    extern __shared__ char smem[];
    __nv_bfloat16* Whi = (__nv_bfloat16*)(smem + OFF_WHI);
    __nv_bfloat16* Wlo = (__nv_bfloat16*)(smem + OFF_WLO);
    float* red = (float*)(smem + OFF_RED);
    float* ghs = (float*)(smem + OFF_GH);

    const int tid = threadIdx.x;
    const int wid = tid >> 5;
    const int lane = tid & 31;
    const int gid = lane >> 2;       // groupID 0..7
    const int tg = lane & 3;         // threadID_in_group 0..3
    const int mtile = wid & 3;       // m offset = mtile*16
    const int khalf = wid >> 2;      // 0 or 1 -> k offset 0 / 64 in chunk
    const int jbase = blockIdx.x * JPB;

    // ---- prologue: convert this block's 24 W rows to bf16 hi/lo in SMEM ----
    for (int idx = tid; idx < 24 * 1024; idx += 256) {
        int n24 = idx >> 10, k = idx & 1023;
        int grow = (n24 >> 3) * NH + jbase + (n24 & 7);
        float x = w_hh[(size_t)grow * NH + k];
        __nv_bfloat16 hi = __float2bfloat16(x);
        __nv_bfloat16 lo = __float2bfloat16(x - __bfloat162float(hi));
        Whi[n24 * WS_STRIDE + k] = hi;
        Wlo[n24 * WS_STRIDE + k] = lo;
    }
    __syncthreads();

    const int use64 = g_y64;
    const int* y32 = (const int*)y_any;
    const long long* y64p = (const long long*)y_any;

    for (int t = 0; t < TT; t++) {
        const int buf = t & 1;
        const float* __restrict__ hcur = g_h[buf];
        float* __restrict__ hnxt = g_h[buf ^ 1];
        const __nv_bfloat16* __restrict__ hbh = g_hbf_hi[buf];
        const __nv_bfloat16* __restrict__ hbl = g_hbf_lo[buf];

        float acc[3][4];
#pragma unroll
        for (int nt = 0; nt < 3; nt++)
#pragma unroll
            for (int q = 0; q < 4; q++) acc[nt][q] = 0.f;

        // ---- stage chunks of H (128 k) hi+lo, 2-stage cp.async pipeline ----
        auto issue = [&](int st, int kc) {
            char* base = smem + OFF_HS + st * HS_STAGE;
#pragma unroll
            for (int r = 0; r < 8; r++) {
                int idx = tid + r * 256;          // 0..2047
                int mat = idx >> 10;              // 0 hi, 1 lo
                int row = (idx >> 4) & 63;
                int seg = idx & 15;
                const __nv_bfloat16* src =
                    (mat ? hbl : hbh) + (size_t)row * NH + kc * 128 + seg * 8;
                cpasync16(base + mat * HS_MAT + row * (HS_STRIDE * 2) + seg * 16, src);
            }
            cpasync_commit();
        };

        issue(0, 0);
        for (int ch = 0; ch < 8; ch++) {
            if (ch + 1 < 8) { issue((ch + 1) & 1, ch + 1); cpasync_wait<1>(); }
            else cpasync_wait<0>();
            __syncthreads();

            const char* sbase = smem + OFF_HS + (ch & 1) * HS_STAGE;
            const __nv_bfloat16* Hhi = (const __nv_bfloat16*)(sbase);
            const __nv_bfloat16* Hlo = (const __nv_bfloat16*)(sbase + HS_MAT);

#pragma unroll
            for (int kk = 0; kk < 4; kk++) {
                const int k0 = khalf * 64 + kk * 16;
                const int r0 = (mtile * 16 + gid) * HS_STRIDE;
                const int r8 = (mtile * 16 + gid + 8) * HS_STRIDE;
                uint32_t ah[4], al[4];
                ah[0] = *(const uint32_t*)&Hhi[r0 + k0 + 2 * tg];
                ah[1] = *(const uint32_t*)&Hhi[r8 + k0 + 2 * tg];
                ah[2] = *(const uint32_t*)&Hhi[r0 + k0 + 2 * tg + 8];
                ah[3] = *(const uint32_t*)&Hhi[r8 + k0 + 2 * tg + 8];
                al[0] = *(const uint32_t*)&Hlo[r0 + k0 + 2 * tg];
                al[1] = *(const uint32_t*)&Hlo[r8 + k0 + 2 * tg];
                al[2] = *(const uint32_t*)&Hlo[r0 + k0 + 2 * tg + 8];
                al[3] = *(const uint32_t*)&Hlo[r8 + k0 + 2 * tg + 8];
                const int kg = ch * 128 + k0;     // global k for W
#pragma unroll
                for (int nt = 0; nt < 3; nt++) {
                    const int wr = (nt * 8 + gid) * WS_STRIDE + kg + 2 * tg;
                    uint32_t bh[2], bl[2];
                    bh[0] = *(const uint32_t*)&Whi[wr];
                    bh[1] = *(const uint32_t*)&Whi[wr + 8];
                    bl[0] = *(const uint32_t*)&Wlo[wr];
                    bl[1] = *(const uint32_t*)&Wlo[wr + 8];
                    mma_bf16(acc[nt], ah, bh);
                    mma_bf16(acc[nt], ah, bl);
                    mma_bf16(acc[nt], al, bh);
                }
            }
            __syncthreads();
        }

        // ---- reduce the two K-halves, materialize GH[64][24] in smem -------
        if (khalf == 1) {
#pragma unroll
            for (int nt = 0; nt < 3; nt++)
#pragma unroll
                for (int q = 0; q < 4; q++)
                    red[(mtile * 32 + lane) * 12 + nt * 4 + q] = acc[nt][q];
        }
        __syncthreads();
        if (khalf == 0) {
#pragma unroll
            for (int nt = 0; nt < 3; nt++) {
#pragma unroll
                for (int q = 0; q < 4; q++)
                    acc[nt][q] += red[(mtile * 32 + lane) * 12 + nt * 4 + q];
                int m_lo = mtile * 16 + gid;
                int n2 = nt * 8 + 2 * tg;
                ghs[m_lo * 24 + n2] = acc[nt][0];
                ghs[m_lo * 24 + n2 + 1] = acc[nt][1];
                ghs[(m_lo + 8) * 24 + n2] = acc[nt][2];
                ghs[(m_lo + 8) * 24 + n2 + 1] = acc[nt][3];
            }
        }
        __syncthreads();

        // ---- gate phase: 512 (batch,unit) pairs, 2 per thread ---------------
#pragma unroll
        for (int pp = 0; pp < 2; pp++) {
            int p = tid + pp * 256;
            int b = p >> 3, u = p & 7;
            int gj = jbase + u;
            int tok = 0;
            if (t > 0) tok = use64 ? (int)y64p[(size_t)b * TT + t - 1]
                                   : y32[(size_t)b * TT + t - 1];
            const float* gi = g_tokgi + (size_t)tok * G3;
            float i_r = gi[gj], i_z = gi[NH + gj], i_n = gi[2 * NH + gj];
            float h_r = ghs[b * 24 + u] + b_hh[gj];
            float h_z = ghs[b * 24 + 8 + u] + b_hh[NH + gj];
            float h_n = ghs[b * 24 + 16 + u] + b_hh[2 * NH + gj];
            float r = 1.f / (1.f + __expf(-(i_r + h_r)));
            float z = 1.f / (1.f + __expf(-(i_z + h_z)));
            float xn = i_n + r * h_n;
            float e2 = __expf(-2.f * xn);
            float n = 2.f / (1.f + e2) - 1.f;
            float hp = hcur[(size_t)b * NH + gj];
            float hn = (1.f - z) * n + z * hp;
            hnxt[(size_t)b * NH + gj] = hn;
            __nv_bfloat16 hi = __float2bfloat16(hn);
            g_hbf_hi[buf ^ 1][(size_t)b * NH + gj] = hi;
            g_hbf_lo[buf ^ 1][(size_t)b * NH + gj] =
                __float2bfloat16(hn - __bfloat162float(hi));
            out_hidden[((size_t)b * TT + t) * NH + gj] = hn;
        }

        grid_barrier((unsigned)(t + 1));
    }
}

// ---------------- in-place log-softmax over V=2048 ---------------------------
__global__ void __launch_bounds__(256) logsoftmax_kernel(float* __restrict__ p) {
    const size_t row = blockIdx.x;
    float* x = p + row * NV;
    const int tid = threadIdx.x;
    float4 v0 = ((const float4*)x)[tid];
    float4 v1 = ((const float4*)x)[tid + 256];
    float m = fmaxf(fmaxf(fmaxf(v0.x, v0.y), fmaxf(v0.z, v0.w)),
                    fmaxf(fmaxf(v1.x, v1.y), fmaxf(v1.z, v1.w)));
    __shared__ float sred[32];
#pragma unroll
    for (int o = 16; o; o >>= 1) m = fmaxf(m, __shfl_xor_sync(0xffffffffu, m, o));
    if ((tid & 31) == 0) sred[tid >> 5] = m;
    __syncthreads();
    if (tid < 32) {
        float t2 = (tid < 8) ? sred[tid] : -3.4e38f;
#pragma unroll
        for (int o = 4; o; o >>= 1) t2 = fmaxf(t2, __shfl_xor_sync(0xffffffffu, t2, o));
        if (tid == 0) sred[0] = t2;
    }
    __syncthreads();
    m = sred[0];
    float s = __expf(v0.x - m) + __expf(v0.y - m) + __expf(v0.z - m) + __expf(v0.w - m)
            + __expf(v1.x - m) + __expf(v1.y - m) + __expf(v1.z - m) + __expf(v1.w - m);
    __syncthreads();
#pragma unroll
    for (int o = 16; o; o >>= 1) s += __shfl_xor_sync(0xffffffffu, s, o);
    if ((tid & 31) == 0) sred[tid >> 5] = s;
    __syncthreads();
    if (tid < 32) {
        float t2 = (tid < 8) ? sred[tid] : 0.f;
#pragma unroll
        for (int o = 4; o; o >>= 1) t2 += __shfl_xor_sync(0xffffffffu, t2, o);
        if (tid == 0) sred[0] = t2;
    }
    __syncthreads();
    float lse = m + logf(sred[0]);
    v0.x -= lse; v0.y -= lse; v0.z -= lse; v0.w -= lse;
    v1.x -= lse; v1.y -= lse; v1.z -= lse; v1.w -= lse;
    ((float4*)x)[tid] = v0;
    ((float4*)x)[tid + 256] = v1;
}

// ---------------- launch ------------------------------------------------------
extern "C" void kernel_launch(void* const* d_in, const int* in_sizes, int n_in,
                              void* d_out, int out_size) {
    int o = (n_in >= 11) ? 1 : 0;
    const float* enc  = (const float*)d_in[0];
    const void*  y    = d_in[1];
    const float* emb  = (const float*)d_in[2 + o];
    const float* brW  = (const float*)d_in[3 + o];
    const float* brb  = (const float*)d_in[4 + o];
    const float* w_ih = (const float*)d_in[5 + o];
    const float* w_hh = (const float*)d_in[6 + o];
    const float* b_ih = (const float*)d_in[7 + o];
    const float* b_hh = (const float*)d_in[8 + o];
    const float* fcW  = (const float*)d_in[9 + o];

    float* out = (float*)d_out;
    float* out_hidden = out;                       // [64,512,1024]
    float* out_logits = out + HID_ELEMS;           // [64,512,2048]

    void* p_h = nullptr;   cudaGetSymbolAddress(&p_h, g_h);
    void* p_tok = nullptr; cudaGetSymbolAddress(&p_tok, g_tokgi);

    static int smem_set = 0;
    if (!smem_set) {
        cudaFuncSetAttribute(gru_scan_tc,
                             cudaFuncAttributeMaxDynamicSharedMemorySize, SMEM_SCAN);
        smem_set = 1;
    }

    dim3 blk(256);
    detect_reset_kernel<<<1, 256>>>((const long long*)y);
    // tokgi[v] = emb[v] @ w_ih^T + b_ih   (fp32)
    sgemm_nt_bias<<<dim3(G3 / 128, NV / 128), blk>>>(emb, w_ih, b_ih,
                                                     (float*)p_tok, NV, G3, 256);
    // h0 = enc @ bridge_W^T + bridge_b    (fp32)
    sgemm_nt_bias<<<dim3(NH / 128, 1), blk>>>(enc, brW, brb,
                                              (float*)p_h, NB, NH, 512);
    // h0 -> bf16 split operands
    h0_convert_kernel<<<64, 256>>>();
    // persistent GRU recurrence (bf16-split tensor cores, exact fp32 state)
    gru_scan_tc<<<SCAN_BLOCKS, 256, SMEM_SCAN>>>(w_hh, b_hh, y, out_hidden);
    // logits = hidden @ fc_W^T  (tf32 tensor cores, in-place)
    gemm_tf32_nt<<<dim3(NV / 128, (NB * TT) / 128), blk>>>(out_hidden, fcW,
                                                           out_logits,
                                                           NB * TT, NV, NH);
    // in-place log-softmax
    logsoftmax_kernel<<<NB * TT, 256>>>(out_logits);
}